// round 14
// baseline (speedup 1.0000x reference)
#include <cuda_runtime.h>
#include <cuda_fp16.h>
#include <cstdint>

#define EMB   1024
#define HEAD  64
#define BATCH 4
#define SEQ   4096
#define NROWS (BATCH*SEQ)   // 16384

// fp16 staging (device globals: no allocs allowed)
__device__ __half g_Qh[NROWS*HEAD];     // Q (pre-scaled by log2e/8), row-major
__device__ __half g_Kh[NROWS*HEAD];     // K row-major [row][dim]
__device__ __half g_Vh[NROWS*HEAD];     // V row-major [row][dim]

#define SW128(o) ((o) ^ (((o) >> 3) & 0x70))
#define ONES_H2 0x3C003C00u   /* half2(1.0, 1.0) */

__device__ __forceinline__ uint32_t smem_u32(const void* p){
    uint32_t a;
    asm("{ .reg .u64 t; cvta.to.shared.u64 t, %1; cvt.u32.u64 %0, t; }" : "=r"(a) : "l"(p));
    return a;
}
__device__ __forceinline__ uint32_t f2h2(float a, float b){
    __half2 h = __floats2half2_rn(a, b);
    return *reinterpret_cast<uint32_t*>(&h);
}
__device__ __forceinline__ uint32_t hexp2_2(uint32_t x){
    uint32_t d;
    asm("ex2.approx.f16x2 %0, %1;" : "=r"(d) : "r"(x));
    return d;
}

#define LDSM_X2(r0, r1, addr) \
    asm volatile("ldmatrix.sync.aligned.m8n8.x2.shared.b16 {%0,%1}, [%2];" \
                 : "=r"(r0), "=r"(r1) : "r"(addr))
#define LDSM_X2T(r0, r1, addr) \
    asm volatile("ldmatrix.sync.aligned.m8n8.x2.trans.shared.b16 {%0,%1}, [%2];" \
                 : "=r"(r0), "=r"(r1) : "r"(addr))
#define LDSM_X4(r0, r1, r2, r3, addr) \
    asm volatile("ldmatrix.sync.aligned.m8n8.x4.shared.b16 {%0,%1,%2,%3}, [%4];" \
                 : "=r"(r0), "=r"(r1), "=r"(r2), "=r"(r3) : "r"(addr))

// D(f32) += A(f16) * B(f16):  m16n8k16, A row-major frag, B col-major frag
#define MMA16816(d, a0, a1, a2, a3, b0, b1) \
    asm volatile("mma.sync.aligned.m16n8k16.row.col.f32.f16.f16.f32 " \
                 "{%0,%1,%2,%3}, {%4,%5,%6,%7}, {%8,%9}, {%0,%1,%2,%3};" \
                 : "+f"((d)[0]), "+f"((d)[1]), "+f"((d)[2]), "+f"((d)[3]) \
                 : "r"(a0), "r"(a1), "r"(a2), "r"(a3), "r"(b0), "r"(b1))

// ---------------------------------------------------------------------------
// Kernel 1: QKV projection, HMMA.  CTA = 128 rows x 192 cols, K chunks of 64.
// 256 threads = 8 warps in 2(M=64) x 4(N=16-per-panel) grid.
// W read fp32 directly (no convert kernel), stored K-major [k][n] in 3 panels,
// B fragments via ldmatrix.x2.trans (same pattern as attn's V path).
// Q is pre-scaled by log2e/8 so attention can use ex2.
// ---------------------------------------------------------------------------
__global__ __launch_bounds__(256)
void proj_kernel(const float* __restrict__ x,
                 const float* __restrict__ Wq, const float* __restrict__ bq,
                 const float* __restrict__ Wk, const float* __restrict__ bk,
                 const float* __restrict__ Wv, const float* __restrict__ bv)
{
    __shared__ __align__(1024) char sm[16384 + 24576];  // x[128][64]h + 3 W panels [64k][64n]h
    __shared__ float bias_s[192];
    char* xsm = sm;
    char* wsm = sm + 16384;   // panel p at wsm + p*8192
    const uint32_t xb = smem_u32(xsm);
    const uint32_t wb = smem_u32(wsm);

    const int tid  = threadIdx.x;
    const int lane = tid & 31;
    const int wid  = tid >> 5;
    const int mw   = wid >> 2;      // 0..1 : M offset mw*64
    const int nw   = wid & 3;       // 0..3 : 16-col group within each panel
    const int g    = lane >> 2;
    const int t4   = lane & 3;
    const int lr   = lane & 7;
    const int q4   = lane >> 3;     // x4 quadrant
    const int sel  = (lane >> 3) & 1;

    const uint32_t lrx      = (uint32_t)(lr * 16);
    const uint32_t xrowoff  = (uint32_t)(((q4 & 1) * 8 + lr) * 128);
    const uint32_t xcolbase = (uint32_t)((q4 >> 1) * 16);
    const uint32_t wrowoff  = (uint32_t)((sel * 8 + lr) * 128);   // trans-B row base

    for (int i = tid; i < 192; i += 256)
        bias_s[i] = (i < 64) ? bq[i] : ((i < 128) ? bk[i - 64] : bv[i - 128]);

    const long row0 = (long)blockIdx.x * 128;
    const int  xrow = tid >> 1;
    const int  xhlf = tid & 1;

    float acc[4][6][4];
#pragma unroll
    for (int mb = 0; mb < 4; mb++)
#pragma unroll
        for (int nb = 0; nb < 6; nb++)
#pragma unroll
            for (int i = 0; i < 4; i++) acc[mb][nb][i] = 0.0f;

    uint4 xh[4];   // x tile slice, fp16-packed at prefetch time
    uint4 wh[6];   // W tile slice, fp16-packed at prefetch time

    // ---- prefetch helpers (convert fp32->fp16 immediately; temps die) ----
    auto fetch_x = [&](int k0, uint4* d){
#pragma unroll
        for (int j = 0; j < 4; j++) {
            const float* s = x + (row0 + xrow) * EMB + k0 + xhlf * 32 + j * 8;
            float4 a = *(const float4*)s;
            float4 c = *(const float4*)(s + 4);
            d[j] = make_uint4(f2h2(a.x, a.y), f2h2(a.z, a.w), f2h2(c.x, c.y), f2h2(c.z, c.w));
        }
    };
    auto fetch_w = [&](int k0, uint4* d){
#pragma unroll
        for (int i = 0; i < 6; i++) {
            int idx = tid + i * 256;           // 0..1535
            int p   = idx >> 9;
            int rem = idx & 511;
            int k   = rem >> 3;
            int ch  = rem & 7;
            const float* W = (p == 0) ? Wq : ((p == 1) ? Wk : Wv);
            const float* s = W + (long)(k0 + k) * HEAD + ch * 8;
            float4 a = *(const float4*)s;
            float4 c = *(const float4*)(s + 4);
            d[i] = make_uint4(f2h2(a.x, a.y), f2h2(a.z, a.w), f2h2(c.x, c.y), f2h2(c.z, c.w));
        }
    };

    fetch_x(0, xh);
    fetch_w(0, wh);

    for (int it = 0; it < 16; it++) {
        if (it) __syncthreads();
        // store prefetched tiles
#pragma unroll
        for (int j = 0; j < 4; j++)
            *(uint4*)(xsm + SW128(xrow * 128 + (xhlf * 4 + j) * 16)) = xh[j];
#pragma unroll
        for (int i = 0; i < 6; i++) {
            int idx = tid + i * 256;
            int p   = idx >> 9;
            int rem = idx & 511;
            int k   = rem >> 3;
            int ch  = rem & 7;
            *(uint4*)(wsm + p * 8192 + SW128(k * 128 + ch * 16)) = wh[i];
        }
        __syncthreads();

        if (it < 15) {
            fetch_x((it + 1) * 64, xh);
            fetch_w((it + 1) * 64, wh);
        }

#pragma unroll
        for (int ks = 0; ks < 4; ks++) {
            uint32_t af[4][4];
#pragma unroll
            for (int mb = 0; mb < 4; mb++) {
                uint32_t addr = xb + (uint32_t)((mw * 64 + mb * 16) * 128) + xrowoff
                              + (((uint32_t)(ks * 32) + xcolbase) ^ lrx);
                LDSM_X4(af[mb][0], af[mb][1], af[mb][2], af[mb][3], addr);
            }
#pragma unroll
            for (int p = 0; p < 3; p++) {
#pragma unroll
                for (int nbi = 0; nbi < 2; nbi++) {
                    uint32_t b0, b1;
                    uint32_t addr = wb + (uint32_t)(p * 8192) + (uint32_t)(ks * 16 * 128) + wrowoff
                                  + (((uint32_t)(nw * 32 + nbi * 16)) ^ lrx);
                    LDSM_X2T(b0, b1, addr);
#pragma unroll
                    for (int mb = 0; mb < 4; mb++)
                        MMA16816(acc[mb][p * 2 + nbi], af[mb][0], af[mb][1], af[mb][2], af[mb][3], b0, b1);
                }
            }
        }
    }

    // epilogue: bias; Q scaled by log2e/8 (exp2-domain softmax downstream)
#pragma unroll
    for (int mb = 0; mb < 4; mb++) {
#pragma unroll
        for (int p = 0; p < 3; p++) {
#pragma unroll
            for (int nbi = 0; nbi < 2; nbi++) {
                int cl = nw * 16 + nbi * 8 + 2 * t4;     // 0..63 within matrix p
                float sc = (p == 0) ? 0.18033688f : 1.0f;   // 0.125 * log2(e)
                __half* dst = (p == 0) ? g_Qh : ((p == 1) ? g_Kh : g_Vh);
                const float* bp = bias_s + p * 64;
                long r0 = row0 + mw * 64 + mb * 16 + g;
                const float* a = acc[mb][p * 2 + nbi];
                float v0 = (a[0] + bp[cl])     * sc;
                float v1 = (a[1] + bp[cl + 1]) * sc;
                float v2 = (a[2] + bp[cl])     * sc;
                float v3 = (a[3] + bp[cl + 1]) * sc;
                *(uint32_t*)(dst + r0 * 64 + cl)       = f2h2(v0, v1);
                *(uint32_t*)(dst + (r0 + 8) * 64 + cl) = f2h2(v2, v3);
            }
        }
    }
}

// ---------------------------------------------------------------------------
// Kernel 2: causal flash attention, HMMA.
// CTA = 64 q-rows; 8 warps = 4(M=16) x 2(key-halves of 32).  2 CTAs/SM.
// Pair-balanced rank mapping: classic scheduler puts bid and bid+148 on the
// SAME SM (LUT[bid%148]); rank = bid<148 ? bid : 403-bid pairs rank r with
// 255-r per SM, so each SM's iteration total is ~constant (~66 vs 91 before).
// exp2-domain softmax on f16x2 MUFU; row-sums l via ones-MMA.
// ---------------------------------------------------------------------------
__global__ __launch_bounds__(256, 2)
void attn_kernel(float* __restrict__ out)
{
    __shared__ __align__(1024) char sm[2 * 16384];   // buf: K 8KB + V 8KB

    const int tid  = threadIdx.x;
    const int lane = tid & 31;
    const int wid  = tid >> 5;
    const int mq   = wid & 3;       // M group: rows mq*16
    const int nq   = wid >> 2;      // key half: keys [nq*32, nq*32+32)
    const int g    = lane >> 2;
    const int t4   = lane & 3;
    const int lr   = lane & 7;
    const int sel  = (lane >> 3) & 1;

    const int bid  = blockIdx.x;                       // 0..255
    const int rank = (bid < 148) ? bid : 403 - bid;    // SM-pair balanced
    const int b    = rank & 3;
    const int qt   = 63 - (rank >> 2);                 // q-tile (64 rows)
    const int qrow0 = qt * 64;
    const int mrow  = mq * 16;

    const uint32_t lrx  = (uint32_t)(lr * 16);

    const int lc1 = tid + 256;
    const int lr0 = tid >> 3, lch0 = tid & 7;
    const int lr1 = lc1 >> 3, lch1 = lc1 & 7;
    const uint32_t soff0 = SW128((uint32_t)(lr0 * 128 + lch0 * 16));
    const uint32_t soff1 = SW128((uint32_t)(lr1 * 128 + lch1 * 16));
    const long goff0 = (long)lr0 * 64 + lch0 * 8;
    const long goff1 = (long)lr1 * 64 + lch1 * 8;

    // Q fragments straight from gmem (fragment layout, once per CTA)
    uint32_t qf[4][4];
    {
        const __half* Qp = g_Qh + ((long)b * SEQ + qrow0 + mrow) * 64;
#pragma unroll
        for (int ks = 0; ks < 4; ks++) {
            qf[ks][0] = *(const uint32_t*)(Qp + (g)     * 64 + ks * 16 + 2 * t4);
            qf[ks][1] = *(const uint32_t*)(Qp + (g + 8) * 64 + ks * 16 + 2 * t4);
            qf[ks][2] = *(const uint32_t*)(Qp + (g)     * 64 + ks * 16 + 8 + 2 * t4);
            qf[ks][3] = *(const uint32_t*)(Qp + (g + 8) * 64 + ks * 16 + 8 + 2 * t4);
        }
    }

    float o_[8][4];
#pragma unroll
    for (int nb = 0; nb < 8; nb++)
#pragma unroll
        for (int i = 0; i < 4; i++) o_[nb][i] = 0.0f;
    float lacc[4] = {0.0f, 0.0f, 0.0f, 0.0f};   // row-sum accumulator (ones-MMA)

    const int nkt = qt + 1;
    const __half* Kb = g_Kh + (long)b * SEQ * 64;
    const __half* Vb = g_Vh + (long)b * SEQ * 64;

    uint4 kreg0 = *(const uint4*)(Kb + goff0);
    uint4 kreg1 = *(const uint4*)(Kb + goff1);
    uint4 vreg0 = *(const uint4*)(Vb + goff0);
    uint4 vreg1 = *(const uint4*)(Vb + goff1);

    for (int kt = 0; kt < nkt; kt++) {
        char* kdst = sm + (kt & 1) * 16384;
        char* vdst = kdst + 8192;
        const uint32_t kb = smem_u32(kdst);
        const uint32_t vb = smem_u32(vdst);

        *(uint4*)(kdst + soff0) = kreg0;
        *(uint4*)(kdst + soff1) = kreg1;
        *(uint4*)(vdst + soff0) = vreg0;
        *(uint4*)(vdst + soff1) = vreg1;
        __syncthreads();

        if (kt + 1 < nkt) {
            const long tb = (long)(kt + 1) * 64 * 64;
            kreg0 = *(const uint4*)(Kb + tb + goff0);
            kreg1 = *(const uint4*)(Kb + tb + goff1);
            vreg0 = *(const uint4*)(Vb + tb + goff0);
            vreg1 = *(const uint4*)(Vb + tb + goff1);
        }

        // ---- MMA1: S[16x32] = Q @ K^T (warp's 32 keys), log2-domain ----
        float s[4][4];
#pragma unroll
        for (int nb = 0; nb < 4; nb++) {
            s[nb][0] = s[nb][1] = s[nb][2] = s[nb][3] = 0.0f;
            uint32_t base = kb + (uint32_t)((nq * 32 + nb * 8 + lr) * 128);
#pragma unroll
            for (int ks = 0; ks < 4; ks++) {
                uint32_t b0, b1;
                LDSM_X2(b0, b1, base + (((uint32_t)(ks * 32 + sel * 16)) ^ lrx));
                MMA16816(s[nb], qf[ks][0], qf[ks][1], qf[ks][2], qf[ks][3], b0, b1);
            }
        }

        // ---- softmax: P = 2^s on f16x2; diagonal tile masked by bit-AND ----
        uint32_t pf[2][4];
        if (kt < qt) {
#pragma unroll
            for (int nb = 0; nb < 4; nb++) {
                int ks2 = nb >> 1, hi = nb & 1;
                pf[ks2][hi * 2]     = hexp2_2(f2h2(s[nb][0], s[nb][1]));  // row g
                pf[ks2][hi * 2 + 1] = hexp2_2(f2h2(s[nb][2], s[nb][3]));  // row g+8
            }
        } else {
            const int jc = kt * 64;
            const int ra = qrow0 + mrow + g;
            const int rb = ra + 8;
#pragma unroll
            for (int nb = 0; nb < 4; nb++) {
                int c0 = jc + nq * 32 + nb * 8 + 2 * t4;
                uint32_t m01 = (c0 <= ra ? 0xFFFFu : 0u) | (c0 + 1 <= ra ? 0xFFFF0000u : 0u);
                uint32_t m23 = (c0 <= rb ? 0xFFFFu : 0u) | (c0 + 1 <= rb ? 0xFFFF0000u : 0u);
                int ks2 = nb >> 1, hi = nb & 1;
                pf[ks2][hi * 2]     = hexp2_2(f2h2(s[nb][0], s[nb][1])) & m01;
                pf[ks2][hi * 2 + 1] = hexp2_2(f2h2(s[nb][2], s[nb][3])) & m23;
            }
        }

        // ---- l row-sums via ones-MMA (C frag holds full row sums) ----
        MMA16816(lacc, pf[0][0], pf[0][1], pf[0][2], pf[0][3], ONES_H2, ONES_H2);
        MMA16816(lacc, pf[1][0], pf[1][1], pf[1][2], pf[1][3], ONES_H2, ONES_H2);

        // ---- MMA2: O += P @ V (warp's 32 keys x all 64 dims) ----
#pragma unroll
        for (int nb = 0; nb < 8; nb++) {
            uint32_t coloff = ((uint32_t)(nb * 16)) ^ lrx;
#pragma unroll
            for (int ks2 = 0; ks2 < 2; ks2++) {
                uint32_t b0, b1;
                uint32_t addr = vb + (uint32_t)((nq * 32 + ks2 * 16 + sel * 8 + lr) * 128) + coloff;
                LDSM_X2T(b0, b1, addr);
                MMA16816(o_[nb], pf[ks2][0], pf[ks2][1], pf[ks2][2], pf[ks2][3], b0, b1);
            }
        }
    }
    __syncthreads();   // all compute done; smem free for exchange

    // ---- merge the two key-half warps (additive: no max-sub) ----
    if (nq == 1) {
        float* dst = (float*)(sm + (mq * 32 + lane) * 144);
#pragma unroll
        for (int nb = 0; nb < 8; nb++)
            ((float4*)dst)[nb] = make_float4(o_[nb][0], o_[nb][1], o_[nb][2], o_[nb][3]);
        dst[32] = lacc[0];
        dst[33] = lacc[2];
    }
    __syncthreads();
    if (nq == 0) {
        const float* src = (const float*)(sm + (mq * 32 + lane) * 144);
#pragma unroll
        for (int nb = 0; nb < 8; nb++) {
            float4 v = ((const float4*)src)[nb];
            o_[nb][0] += v.x; o_[nb][1] += v.y; o_[nb][2] += v.z; o_[nb][3] += v.w;
        }
        const float inv0 = 1.0f / (lacc[0] + src[32]);
        const float inv1 = 1.0f / (lacc[2] + src[33]);

        float* op = out + ((long)b * SEQ + qrow0 + mrow) * 64;
#pragma unroll
        for (int nb = 0; nb < 8; nb++) {
            int c = nb * 8 + 2 * t4;
            float2 v0 = make_float2(o_[nb][0] * inv0, o_[nb][1] * inv0);
            float2 v1 = make_float2(o_[nb][2] * inv1, o_[nb][3] * inv1);
            *(float2*)(op + (g)     * 64 + c) = v0;
            *(float2*)(op + (g + 8) * 64 + c) = v1;
        }
    }
}

// ---------------------------------------------------------------------------
extern "C" void kernel_launch(void* const* d_in, const int* in_sizes, int n_in,
                              void* d_out, int out_size)
{
    (void)in_sizes; (void)n_in; (void)out_size;
    const float* x  = (const float*)d_in[0];
    const float* Wq = (const float*)d_in[1];
    const float* bq = (const float*)d_in[2];
    const float* Wk = (const float*)d_in[3];
    const float* bk = (const float*)d_in[4];
    const float* Wv = (const float*)d_in[5];
    const float* bv = (const float*)d_in[6];
    float* out = (float*)d_out;

    proj_kernel<<<NROWS / 128, 256>>>(x, Wq, bq, Wk, bk, Wv, bv);
    attn_kernel<<<256, 256>>>(out);
}

// round 15
// speedup vs baseline: 1.1128x; 1.1128x over previous
#include <cuda_runtime.h>
#include <cuda_fp16.h>
#include <cstdint>

#define EMB   1024
#define HEAD  64
#define BATCH 4
#define SEQ   4096
#define NROWS (BATCH*SEQ)   // 16384

// fp16 staging (device globals: no allocs allowed)
__device__ __half g_Wh[3*EMB*HEAD];     // W fp16, same [k][n] layout as source
__device__ __half g_Qh[NROWS*HEAD];     // Q (pre-scaled by log2e/8), row-major
__device__ __half g_Kh[NROWS*HEAD];     // K row-major [row][dim]
__device__ __half g_Vh[NROWS*HEAD];     // V row-major [row][dim]

#define SW128(o) ((o) ^ (((o) >> 3) & 0x70))
#define ONES_H2 0x3C003C00u   /* half2(1.0, 1.0) */

__device__ __forceinline__ uint32_t smem_u32(const void* p){
    uint32_t a;
    asm("{ .reg .u64 t; cvta.to.shared.u64 t, %1; cvt.u32.u64 %0, t; }" : "=r"(a) : "l"(p));
    return a;
}
__device__ __forceinline__ uint32_t f2h2(float a, float b){
    __half2 h = __floats2half2_rn(a, b);
    return *reinterpret_cast<uint32_t*>(&h);
}
__device__ __forceinline__ uint32_t hexp2_2(uint32_t x){
    uint32_t d;
    asm("ex2.approx.f16x2 %0, %1;" : "=r"(d) : "r"(x));
    return d;
}

#define LDSM_X2(r0, r1, addr) \
    asm volatile("ldmatrix.sync.aligned.m8n8.x2.shared.b16 {%0,%1}, [%2];" \
                 : "=r"(r0), "=r"(r1) : "r"(addr))
#define LDSM_X2T(r0, r1, addr) \
    asm volatile("ldmatrix.sync.aligned.m8n8.x2.trans.shared.b16 {%0,%1}, [%2];" \
                 : "=r"(r0), "=r"(r1) : "r"(addr))
#define LDSM_X4(r0, r1, r2, r3, addr) \
    asm volatile("ldmatrix.sync.aligned.m8n8.x4.shared.b16 {%0,%1,%2,%3}, [%4];" \
                 : "=r"(r0), "=r"(r1), "=r"(r2), "=r"(r3) : "r"(addr))

// D(f32) += A(f16) * B(f16):  m16n8k16, A row-major frag, B col-major frag
#define MMA16816(d, a0, a1, a2, a3, b0, b1) \
    asm volatile("mma.sync.aligned.m16n8k16.row.col.f32.f16.f16.f32 " \
                 "{%0,%1,%2,%3}, {%4,%5,%6,%7}, {%8,%9}, {%0,%1,%2,%3};" \
                 : "+f"((d)[0]), "+f"((d)[1]), "+f"((d)[2]), "+f"((d)[3]) \
                 : "r"(a0), "r"(a1), "r"(a2), "r"(a3), "r"(b0), "r"(b1))

// ---------------------------------------------------------------------------
// Kernel 0: W fp32 -> fp16, elementwise, NO transpose (W is already [k][n]).
// 24576 threads x 8 elems; fully coalesced float4 reads / uint4 writes.
// ---------------------------------------------------------------------------
__global__ void convert_w_kernel(const float* __restrict__ Wq,
                                 const float* __restrict__ Wk,
                                 const float* __restrict__ Wv)
{
    int id  = blockIdx.x * 256 + threadIdx.x;   // 0..24575
    int p   = id >> 13;                          // 0..2
    int rem = id & 8191;                         // element-octet within matrix
    const float* W = (p == 0) ? Wq : ((p == 1) ? Wk : Wv);
    const float* s = W + (long)rem * 8;
    float4 a = *(const float4*)s;
    float4 c = *(const float4*)(s + 4);
    uint4 u = make_uint4(f2h2(a.x, a.y), f2h2(a.z, a.w), f2h2(c.x, c.y), f2h2(c.z, c.w));
    *(uint4*)(g_Wh + (long)p * 65536 + (long)rem * 8) = u;
}

// ---------------------------------------------------------------------------
// Kernel 1: QKV projection, HMMA.  CTA = 64 rows x 192 cols, K chunks of 64.
// Grid 256, 2 CTAs/SM.  8 warps = 2(M=32, two m16 blocks) x 4(N-groups).
// W read fp16 from g_Wh; B fragments via ldmatrix.x2.trans.
// Q is pre-scaled by log2e/8 so attention can use ex2.
// ---------------------------------------------------------------------------
__global__ __launch_bounds__(256, 2)
void proj_kernel(const float* __restrict__ x,
                 const float* __restrict__ bq,
                 const float* __restrict__ bk,
                 const float* __restrict__ bv)
{
    __shared__ __align__(1024) char sm[8192 + 24576];  // x[64][64]h + 3 W panels [64k][64n]h
    __shared__ float bias_s[192];
    char* xsm = sm;
    char* wsm = sm + 8192;   // panel p at wsm + p*8192
    const uint32_t xb = smem_u32(xsm);
    const uint32_t wb = smem_u32(wsm);

    const int tid  = threadIdx.x;
    const int lane = tid & 31;
    const int wid  = tid >> 5;
    const int mw   = wid >> 2;      // 0..1 : M offset mw*32
    const int nw   = wid & 3;       // 0..3 : 16-col group within each panel
    const int g    = lane >> 2;
    const int t4   = lane & 3;
    const int lr   = lane & 7;
    const int q4   = lane >> 3;     // x4 quadrant
    const int sel  = (lane >> 3) & 1;

    const uint32_t lrx      = (uint32_t)(lr * 16);
    const uint32_t xrowoff  = (uint32_t)(((q4 & 1) * 8 + lr) * 128);
    const uint32_t xcolbase = (uint32_t)((q4 >> 1) * 16);
    const uint32_t wrowoff  = (uint32_t)((sel * 8 + lr) * 128);   // trans-B row base

    for (int i = tid; i < 192; i += 256)
        bias_s[i] = (i < 64) ? bq[i] : ((i < 128) ? bk[i - 64] : bv[i - 128]);

    const long row0 = (long)blockIdx.x * 64;
    const int  xrow = tid >> 2;          // 0..63 : row in x tile
    const int  xc2  = (tid & 3) * 2;     // first of two 16B chunks this thread owns

    float acc[2][6][4];
#pragma unroll
    for (int mb = 0; mb < 2; mb++)
#pragma unroll
        for (int nb = 0; nb < 6; nb++)
#pragma unroll
            for (int i = 0; i < 4; i++) acc[mb][nb][i] = 0.0f;

    uint4 xh[2];   // x tile slice, fp16-packed at prefetch time
    uint4 wh[6];   // W tile slice (already fp16 in gmem)

    auto fetch_x = [&](int k0, uint4* d){
#pragma unroll
        for (int j = 0; j < 2; j++) {
            const float* s = x + (row0 + xrow) * EMB + k0 + (xc2 + j) * 8;
            float4 a = *(const float4*)s;
            float4 c = *(const float4*)(s + 4);
            d[j] = make_uint4(f2h2(a.x, a.y), f2h2(a.z, a.w), f2h2(c.x, c.y), f2h2(c.z, c.w));
        }
    };
    auto fetch_w = [&](int k0, uint4* d){
#pragma unroll
        for (int i = 0; i < 6; i++) {
            int idx = tid + i * 256;           // 0..1535
            int p   = idx >> 9;
            int rem = idx & 511;
            int k   = rem >> 3;
            int ch  = rem & 7;
            d[i] = *(const uint4*)(g_Wh + (long)p * 65536 + (long)(k0 + k) * 64 + ch * 8);
        }
    };

    fetch_x(0, xh);
    fetch_w(0, wh);

    for (int it = 0; it < 16; it++) {
        if (it) __syncthreads();
        // store prefetched tiles
#pragma unroll
        for (int j = 0; j < 2; j++)
            *(uint4*)(xsm + SW128(xrow * 128 + (xc2 + j) * 16)) = xh[j];
#pragma unroll
        for (int i = 0; i < 6; i++) {
            int idx = tid + i * 256;
            int p   = idx >> 9;
            int rem = idx & 511;
            int k   = rem >> 3;
            int ch  = rem & 7;
            *(uint4*)(wsm + p * 8192 + SW128(k * 128 + ch * 16)) = wh[i];
        }
        __syncthreads();

        if (it < 15) {
            fetch_x((it + 1) * 64, xh);
            fetch_w((it + 1) * 64, wh);
        }

#pragma unroll
        for (int ks = 0; ks < 4; ks++) {
            uint32_t af[2][4];
#pragma unroll
            for (int mb = 0; mb < 2; mb++) {
                uint32_t addr = xb + (uint32_t)((mw * 32 + mb * 16) * 128) + xrowoff
                              + (((uint32_t)(ks * 32) + xcolbase) ^ lrx);
                LDSM_X4(af[mb][0], af[mb][1], af[mb][2], af[mb][3], addr);
            }
#pragma unroll
            for (int p = 0; p < 3; p++) {
#pragma unroll
                for (int nbi = 0; nbi < 2; nbi++) {
                    uint32_t b0, b1;
                    uint32_t addr = wb + (uint32_t)(p * 8192) + (uint32_t)(ks * 16 * 128) + wrowoff
                                  + (((uint32_t)(nw * 32 + nbi * 16)) ^ lrx);
                    LDSM_X2T(b0, b1, addr);
#pragma unroll
                    for (int mb = 0; mb < 2; mb++)
                        MMA16816(acc[mb][p * 2 + nbi], af[mb][0], af[mb][1], af[mb][2], af[mb][3], b0, b1);
                }
            }
        }
    }

    // epilogue: bias; Q scaled by log2e/8 (exp2-domain softmax downstream)
#pragma unroll
    for (int mb = 0; mb < 2; mb++) {
#pragma unroll
        for (int p = 0; p < 3; p++) {
#pragma unroll
            for (int nbi = 0; nbi < 2; nbi++) {
                int cl = nw * 16 + nbi * 8 + 2 * t4;     // 0..63 within matrix p
                float sc = (p == 0) ? 0.18033688f : 1.0f;   // 0.125 * log2(e)
                __half* dst = (p == 0) ? g_Qh : ((p == 1) ? g_Kh : g_Vh);
                const float* bp = bias_s + p * 64;
                long r0 = row0 + mw * 32 + mb * 16 + g;
                const float* a = acc[mb][p * 2 + nbi];
                float v0 = (a[0] + bp[cl])     * sc;
                float v1 = (a[1] + bp[cl + 1]) * sc;
                float v2 = (a[2] + bp[cl])     * sc;
                float v3 = (a[3] + bp[cl + 1]) * sc;
                *(uint32_t*)(dst + r0 * 64 + cl)       = f2h2(v0, v1);
                *(uint32_t*)(dst + (r0 + 8) * 64 + cl) = f2h2(v2, v3);
            }
        }
    }
}

// ---------------------------------------------------------------------------
// Kernel 2: causal flash attention, HMMA.  (unchanged from R14: 53.3us)
// CTA = 64 q-rows; 8 warps = 4(M=16) x 2(key-halves of 32).  2 CTAs/SM.
// Pair-balanced rank mapping over the bid%148 same-SM pairing.
// exp2-domain softmax on f16x2 MUFU; row-sums l via ones-MMA.
// ---------------------------------------------------------------------------
__global__ __launch_bounds__(256, 2)
void attn_kernel(float* __restrict__ out)
{
    __shared__ __align__(1024) char sm[2 * 16384];   // buf: K 8KB + V 8KB

    const int tid  = threadIdx.x;
    const int lane = tid & 31;
    const int wid  = tid >> 5;
    const int mq   = wid & 3;       // M group: rows mq*16
    const int nq   = wid >> 2;      // key half: keys [nq*32, nq*32+32)
    const int g    = lane >> 2;
    const int t4   = lane & 3;
    const int lr   = lane & 7;
    const int sel  = (lane >> 3) & 1;

    const int bid  = blockIdx.x;                       // 0..255
    const int rank = (bid < 148) ? bid : 403 - bid;    // SM-pair balanced
    const int b    = rank & 3;
    const int qt   = 63 - (rank >> 2);                 // q-tile (64 rows)
    const int qrow0 = qt * 64;
    const int mrow  = mq * 16;

    const uint32_t lrx  = (uint32_t)(lr * 16);

    const int lc1 = tid + 256;
    const int lr0 = tid >> 3, lch0 = tid & 7;
    const int lr1 = lc1 >> 3, lch1 = lc1 & 7;
    const uint32_t soff0 = SW128((uint32_t)(lr0 * 128 + lch0 * 16));
    const uint32_t soff1 = SW128((uint32_t)(lr1 * 128 + lch1 * 16));
    const long goff0 = (long)lr0 * 64 + lch0 * 8;
    const long goff1 = (long)lr1 * 64 + lch1 * 8;

    // Q fragments straight from gmem (fragment layout, once per CTA)
    uint32_t qf[4][4];
    {
        const __half* Qp = g_Qh + ((long)b * SEQ + qrow0 + mrow) * 64;
#pragma unroll
        for (int ks = 0; ks < 4; ks++) {
            qf[ks][0] = *(const uint32_t*)(Qp + (g)     * 64 + ks * 16 + 2 * t4);
            qf[ks][1] = *(const uint32_t*)(Qp + (g + 8) * 64 + ks * 16 + 2 * t4);
            qf[ks][2] = *(const uint32_t*)(Qp + (g)     * 64 + ks * 16 + 8 + 2 * t4);
            qf[ks][3] = *(const uint32_t*)(Qp + (g + 8) * 64 + ks * 16 + 8 + 2 * t4);
        }
    }

    float o_[8][4];
#pragma unroll
    for (int nb = 0; nb < 8; nb++)
#pragma unroll
        for (int i = 0; i < 4; i++) o_[nb][i] = 0.0f;
    float lacc[4] = {0.0f, 0.0f, 0.0f, 0.0f};   // row-sum accumulator (ones-MMA)

    const int nkt = qt + 1;
    const __half* Kb = g_Kh + (long)b * SEQ * 64;
    const __half* Vb = g_Vh + (long)b * SEQ * 64;

    uint4 kreg0 = *(const uint4*)(Kb + goff0);
    uint4 kreg1 = *(const uint4*)(Kb + goff1);
    uint4 vreg0 = *(const uint4*)(Vb + goff0);
    uint4 vreg1 = *(const uint4*)(Vb + goff1);

    for (int kt = 0; kt < nkt; kt++) {
        char* kdst = sm + (kt & 1) * 16384;
        char* vdst = kdst + 8192;
        const uint32_t kb = smem_u32(kdst);
        const uint32_t vb = smem_u32(vdst);

        *(uint4*)(kdst + soff0) = kreg0;
        *(uint4*)(kdst + soff1) = kreg1;
        *(uint4*)(vdst + soff0) = vreg0;
        *(uint4*)(vdst + soff1) = vreg1;
        __syncthreads();

        if (kt + 1 < nkt) {
            const long tb = (long)(kt + 1) * 64 * 64;
            kreg0 = *(const uint4*)(Kb + tb + goff0);
            kreg1 = *(const uint4*)(Kb + tb + goff1);
            vreg0 = *(const uint4*)(Vb + tb + goff0);
            vreg1 = *(const uint4*)(Vb + tb + goff1);
        }

        // ---- MMA1: S[16x32] = Q @ K^T (warp's 32 keys), log2-domain ----
        float s[4][4];
#pragma unroll
        for (int nb = 0; nb < 4; nb++) {
            s[nb][0] = s[nb][1] = s[nb][2] = s[nb][3] = 0.0f;
            uint32_t base = kb + (uint32_t)((nq * 32 + nb * 8 + lr) * 128);
#pragma unroll
            for (int ks = 0; ks < 4; ks++) {
                uint32_t b0, b1;
                LDSM_X2(b0, b1, base + (((uint32_t)(ks * 32 + sel * 16)) ^ lrx));
                MMA16816(s[nb], qf[ks][0], qf[ks][1], qf[ks][2], qf[ks][3], b0, b1);
            }
        }

        // ---- softmax: P = 2^s on f16x2; diagonal tile masked by bit-AND ----
        uint32_t pf[2][4];
        if (kt < qt) {
#pragma unroll
            for (int nb = 0; nb < 4; nb++) {
                int ks2 = nb >> 1, hi = nb & 1;
                pf[ks2][hi * 2]     = hexp2_2(f2h2(s[nb][0], s[nb][1]));  // row g
                pf[ks2][hi * 2 + 1] = hexp2_2(f2h2(s[nb][2], s[nb][3]));  // row g+8
            }
        } else {
            const int jc = kt * 64;
            const int ra = qrow0 + mrow + g;
            const int rb = ra + 8;
#pragma unroll
            for (int nb = 0; nb < 4; nb++) {
                int c0 = jc + nq * 32 + nb * 8 + 2 * t4;
                uint32_t m01 = (c0 <= ra ? 0xFFFFu : 0u) | (c0 + 1 <= ra ? 0xFFFF0000u : 0u);
                uint32_t m23 = (c0 <= rb ? 0xFFFFu : 0u) | (c0 + 1 <= rb ? 0xFFFF0000u : 0u);
                int ks2 = nb >> 1, hi = nb & 1;
                pf[ks2][hi * 2]     = hexp2_2(f2h2(s[nb][0], s[nb][1])) & m01;
                pf[ks2][hi * 2 + 1] = hexp2_2(f2h2(s[nb][2], s[nb][3])) & m23;
            }
        }

        // ---- l row-sums via ones-MMA (C frag holds full row sums) ----
        MMA16816(lacc, pf[0][0], pf[0][1], pf[0][2], pf[0][3], ONES_H2, ONES_H2);
        MMA16816(lacc, pf[1][0], pf[1][1], pf[1][2], pf[1][3], ONES_H2, ONES_H2);

        // ---- MMA2: O += P @ V (warp's 32 keys x all 64 dims) ----
#pragma unroll
        for (int nb = 0; nb < 8; nb++) {
            uint32_t coloff = ((uint32_t)(nb * 16)) ^ lrx;
#pragma unroll
            for (int ks2 = 0; ks2 < 2; ks2++) {
                uint32_t b0, b1;
                uint32_t addr = vb + (uint32_t)((nq * 32 + ks2 * 16 + sel * 8 + lr) * 128) + coloff;
                LDSM_X2T(b0, b1, addr);
                MMA16816(o_[nb], pf[ks2][0], pf[ks2][1], pf[ks2][2], pf[ks2][3], b0, b1);
            }
        }
    }
    __syncthreads();   // all compute done; smem free for exchange

    // ---- merge the two key-half warps (additive: no max-sub) ----
    if (nq == 1) {
        float* dst = (float*)(sm + (mq * 32 + lane) * 144);
#pragma unroll
        for (int nb = 0; nb < 8; nb++)
            ((float4*)dst)[nb] = make_float4(o_[nb][0], o_[nb][1], o_[nb][2], o_[nb][3]);
        dst[32] = lacc[0];
        dst[33] = lacc[2];
    }
    __syncthreads();
    if (nq == 0) {
        const float* src = (const float*)(sm + (mq * 32 + lane) * 144);
#pragma unroll
        for (int nb = 0; nb < 8; nb++) {
            float4 v = ((const float4*)src)[nb];
            o_[nb][0] += v.x; o_[nb][1] += v.y; o_[nb][2] += v.z; o_[nb][3] += v.w;
        }
        const float inv0 = 1.0f / (lacc[0] + src[32]);
        const float inv1 = 1.0f / (lacc[2] + src[33]);

        float* op = out + ((long)b * SEQ + qrow0 + mrow) * 64;
#pragma unroll
        for (int nb = 0; nb < 8; nb++) {
            int c = nb * 8 + 2 * t4;
            float2 v0 = make_float2(o_[nb][0] * inv0, o_[nb][1] * inv0);
            float2 v1 = make_float2(o_[nb][2] * inv1, o_[nb][3] * inv1);
            *(float2*)(op + (g)     * 64 + c) = v0;
            *(float2*)(op + (g + 8) * 64 + c) = v1;
        }
    }
}

// ---------------------------------------------------------------------------
extern "C" void kernel_launch(void* const* d_in, const int* in_sizes, int n_in,
                              void* d_out, int out_size)
{
    (void)in_sizes; (void)n_in; (void)out_size;
    const float* x  = (const float*)d_in[0];
    const float* Wq = (const float*)d_in[1];
    const float* bq = (const float*)d_in[2];
    const float* Wk = (const float*)d_in[3];
    const float* bk = (const float*)d_in[4];
    const float* Wv = (const float*)d_in[5];
    const float* bv = (const float*)d_in[6];
    float* out = (float*)d_out;

    convert_w_kernel<<<96, 256>>>(Wq, Wk, Wv);
    proj_kernel<<<NROWS / 64, 256>>>(x, bq, bk, bv);
    attn_kernel<<<256, 256>>>(out);
}